// round 1
// baseline (speedup 1.0000x reference)
#include <cuda_runtime.h>
#include <cuda_bf16.h>
#include <cstdint>

#define NN 100000
#define DD 128

// ---------------- scratch (device globals; no allocation allowed) ------------
__device__ float g_deg[NN];
__device__ float g_dinv[NN];
__device__ float g_h[(size_t)NN * DD];    // current layer's X @ W
__device__ float g_y[(size_t)NN * DD];    // layer-1 activation output
__device__ float g_agg[(size_t)NN * DD];  // aggregation accumulator
__device__ int   g_is64;                  // edge_index dtype flag

// ---------------- helpers ----------------------------------------------------
__device__ __forceinline__ void red_add_v4(float* addr, float4 v) {
    // sm_90+ vectorized global reduction (no return) — cheapest scatter path
    asm volatile("red.global.add.v4.f32 [%0], {%1,%2,%3,%4};"
                 :: "l"(addr), "f"(v.x), "f"(v.y), "f"(v.z), "f"(v.w)
                 : "memory");
}

// ---------------- kernels ----------------------------------------------------

// Detect whether edge_index is int64 or int32. Values are < 100000, so as
// int64 every odd 32-bit word is 0. 64 random int32 indices being all zero
// has probability ~0.
__global__ void detect_kernel(const int* __restrict__ ei) {
    if (threadIdx.x == 0) {
        int ok = 1;
        #pragma unroll
        for (int i = 1; i < 128; i += 2)
            if (ei[i] != 0) ok = 0;
        g_is64 = ok;
    }
}

__global__ void deg_init_kernel(int n) {
    int i = blockIdx.x * blockDim.x + threadIdx.x;
    if (i < n) g_deg[i] = 1.0f;  // self-loop weight 1
}

__global__ void deg_edge_kernel(const void* __restrict__ ei,
                                const float* __restrict__ ew, int E) {
    int e = blockIdx.x * blockDim.x + threadIdx.x;
    if (e >= E) return;
    long long d;
    if (g_is64) d = ((const long long*)ei)[E + e];
    else        d = ((const int*)ei)[E + e];
    atomicAdd(&g_deg[d], ew[e]);
}

__global__ void dinv_kernel(int n) {
    int i = blockIdx.x * blockDim.x + threadIdx.x;
    if (i < n) {
        float dg = g_deg[i];
        g_dinv[i] = (dg > 0.0f) ? rsqrtf(dg) : 0.0f;
    }
}

// H[n,128] = X[n,128] @ W[128,128].  One warp computes 2 rows.
// Lane l holds x[row][4l..4l+3] as a float4; x[k] broadcast via shfl.
// W rows read via __ldg (W = 64 KB, L1-resident); X streamed with __ldcs.
__global__ void gemm128_kernel(const float* __restrict__ X,
                               const float* __restrict__ W,
                               float* __restrict__ H, int n) {
    int warp = (blockIdx.x * blockDim.x + threadIdx.x) >> 5;
    int lane = threadIdx.x & 31;
    int r0 = warp * 2;
    if (r0 >= n) return;
    int r1 = (r0 + 1 < n) ? (r0 + 1) : r0;

    const float4* X4 = (const float4*)X;
    const float4* W4 = (const float4*)W;
    float4 xa = __ldcs(X4 + (size_t)r0 * 32 + lane);
    float4 xb = __ldcs(X4 + (size_t)r1 * 32 + lane);

    float4 acc0 = make_float4(0.f, 0.f, 0.f, 0.f);
    float4 acc1 = make_float4(0.f, 0.f, 0.f, 0.f);

    #pragma unroll 4
    for (int kb = 0; kb < 32; kb++) {
        float a0 = __shfl_sync(0xffffffffu, xa.x, kb);
        float a1 = __shfl_sync(0xffffffffu, xa.y, kb);
        float a2 = __shfl_sync(0xffffffffu, xa.z, kb);
        float a3 = __shfl_sync(0xffffffffu, xa.w, kb);
        float b0 = __shfl_sync(0xffffffffu, xb.x, kb);
        float b1 = __shfl_sync(0xffffffffu, xb.y, kb);
        float b2 = __shfl_sync(0xffffffffu, xb.z, kb);
        float b3 = __shfl_sync(0xffffffffu, xb.w, kb);
        float av[4] = {a0, a1, a2, a3};
        float bv[4] = {b0, b1, b2, b3};
        #pragma unroll
        for (int c = 0; c < 4; c++) {
            float4 w = __ldg(W4 + (size_t)(kb * 4 + c) * 32 + lane);
            float ax = av[c], bx = bv[c];
            acc0.x += ax * w.x; acc0.y += ax * w.y;
            acc0.z += ax * w.z; acc0.w += ax * w.w;
            acc1.x += bx * w.x; acc1.y += bx * w.y;
            acc1.z += bx * w.z; acc1.w += bx * w.w;
        }
    }
    ((float4*)H)[(size_t)r0 * 32 + lane] = acc0;
    if (r1 != r0) ((float4*)H)[(size_t)r1 * 32 + lane] = acc1;
}

// agg = h * dinv^2  (self-loop contribution baked into the accumulator init)
__global__ void init_agg_kernel(const float* __restrict__ h,
                                float* __restrict__ agg, int n) {
    size_t t = (size_t)blockIdx.x * blockDim.x + threadIdx.x;  // float4 index
    if (t >= (size_t)n * 32) return;
    int i = (int)(t >> 5);
    float dv = g_dinv[i];
    float s = dv * dv;
    float4 hv = ((const float4*)h)[t];
    hv.x *= s; hv.y *= s; hv.z *= s; hv.w *= s;
    ((float4*)agg)[t] = hv;
}

// One warp per edge: agg[dst] += h[src] * (dinv[src]*w*dinv[dst])
__global__ void edge_agg_kernel(const void* __restrict__ ei,
                                const float* __restrict__ ew,
                                const float* __restrict__ h,
                                float* __restrict__ agg, int E) {
    int e = (int)(((size_t)blockIdx.x * blockDim.x + threadIdx.x) >> 5);
    int lane = threadIdx.x & 31;
    if (e >= E) return;
    long long s, d;
    if (g_is64) {
        const long long* p = (const long long*)ei;
        s = p[e]; d = p[E + e];
    } else {
        const int* p = (const int*)ei;
        s = p[e]; d = p[E + e];
    }
    float norm = g_dinv[s] * ew[e] * g_dinv[d];
    float4 hv = ((const float4*)(h + s * (size_t)DD))[lane];
    hv.x *= norm; hv.y *= norm; hv.z *= norm; hv.w *= norm;
    red_add_v4((float*)((float4*)(agg + d * (size_t)DD) + lane), hv);
}

// out = relu(agg + b)
__global__ void finalize_kernel(const float* __restrict__ agg,
                                const float* __restrict__ b,
                                float* __restrict__ out, int n) {
    size_t t = (size_t)blockIdx.x * blockDim.x + threadIdx.x;  // float4 index
    if (t >= (size_t)n * 32) return;
    int j4 = (int)(t & 31);
    float4 bv = ((const float4*)b)[j4];
    float4 a = ((const float4*)agg)[t];
    a.x = fmaxf(a.x + bv.x, 0.f);
    a.y = fmaxf(a.y + bv.y, 0.f);
    a.z = fmaxf(a.z + bv.z, 0.f);
    a.w = fmaxf(a.w + bv.w, 0.f);
    ((float4*)out)[t] = a;
}

// ---------------- launch -----------------------------------------------------
extern "C" void kernel_launch(void* const* d_in, const int* in_sizes, int n_in,
                              void* d_out, int out_size) {
    const float* x  = (const float*)d_in[0];
    const void*  ei = d_in[1];
    const float* ew = (const float*)d_in[2];
    const float* W1 = (const float*)d_in[3];
    const float* b1 = (const float*)d_in[4];
    const float* W2 = (const float*)d_in[5];
    const float* b2 = (const float*)d_in[6];
    float* out = (float*)d_out;

    const int N = in_sizes[0] / DD;   // 100000
    const int E = in_sizes[2];        // 1600000

    float* h   = nullptr; cudaGetSymbolAddress((void**)&h,   g_h);
    float* y   = nullptr; cudaGetSymbolAddress((void**)&y,   g_y);
    float* agg = nullptr; cudaGetSymbolAddress((void**)&agg, g_agg);

    const int T = 256;
    int nodeBlocks  = (N + T - 1) / T;
    int edgeBlocks  = (E + T - 1) / T;
    int elemBlocks  = (int)(((size_t)N * 32 + T - 1) / T);      // float4 elems
    int gemmBlocks  = ((N + 1) / 2 * 32 + T - 1) / T;           // 2 rows/warp
    int edgeWarpBlk = (int)(((size_t)E * 32 + T - 1) / T);      // warp/edge

    // degree / normalization (identical for both layers)
    detect_kernel<<<1, 32>>>((const int*)ei);
    deg_init_kernel<<<nodeBlocks, T>>>(N);
    deg_edge_kernel<<<edgeBlocks, T>>>(ei, ew, E);
    dinv_kernel<<<nodeBlocks, T>>>(N);

    // ---- layer 1 ----
    gemm128_kernel<<<gemmBlocks, T>>>(x, W1, h, N);
    init_agg_kernel<<<elemBlocks, T>>>(h, agg, N);
    edge_agg_kernel<<<edgeWarpBlk, T>>>(ei, ew, h, agg, E);
    finalize_kernel<<<elemBlocks, T>>>(agg, b1, y, N);

    // ---- layer 2 ----
    gemm128_kernel<<<gemmBlocks, T>>>(y, W2, h, N);
    init_agg_kernel<<<elemBlocks, T>>>(h, agg, N);
    edge_agg_kernel<<<edgeWarpBlk, T>>>(ei, ew, h, agg, E);
    finalize_kernel<<<elemBlocks, T>>>(agg, b2, out, N);
}

// round 2
// speedup vs baseline: 1.8797x; 1.8797x over previous
#include <cuda_runtime.h>
#include <cuda_bf16.h>
#include <cstdint>

#define NN 100000
#define EE 1664000   // capacity margin over 1,600,000
#define DD 128

// ---------------- scratch (device globals; no allocation allowed) ------------
__device__ float g_deg[NN];
__device__ float g_dinv[NN];
__device__ int   g_cnt[NN];
__device__ int   g_rowptr[NN + 1];
__device__ int   g_fill[NN];
__device__ int   g_bsum[128];     // per-block sums for scan (98 used)
__device__ int   g_boff[128];
__device__ int   g_srcs[EE];      // CSR: src per edge, grouped by dst
__device__ float g_norms[EE];     // CSR: dinv[s]*w*dinv[d] per edge
__device__ float g_h[(size_t)NN * DD];   // current layer's X @ W
__device__ float g_y[(size_t)NN * DD];   // layer-1 activation output
__device__ int   g_is64;

// ---------------- helpers ----------------------------------------------------
__device__ __forceinline__ unsigned long long pack2(float v) {
    unsigned long long r;
    asm("mov.b64 %0, {%1, %1};" : "=l"(r) : "f"(v));
    return r;
}
__device__ __forceinline__ void ffma2(unsigned long long& d,
                                      unsigned long long a,
                                      unsigned long long b) {
    asm("fma.rn.f32x2 %0, %1, %2, %0;" : "+l"(d) : "l"(a), "l"(b));
}

// ---------------- preprocessing ----------------------------------------------

// edge_index dtype sniff: int64 values < 1e5 -> every odd 32-bit word is 0
__global__ void detect_kernel(const int* __restrict__ ei) {
    if (threadIdx.x == 0) {
        int ok = 1;
        #pragma unroll
        for (int i = 1; i < 128; i += 2)
            if (ei[i] != 0) ok = 0;
        g_is64 = ok;
    }
}

__global__ void node_init_kernel(int n) {
    int i = blockIdx.x * blockDim.x + threadIdx.x;
    if (i < n) { g_deg[i] = 1.0f; g_cnt[i] = 0; }  // self-loop weight 1
}

// degree (weighted, at dst) + histogram (edge count per dst)
__global__ void deg_edge_kernel(const int* __restrict__ ei,
                                const float* __restrict__ ew, int E) {
    int e = blockIdx.x * blockDim.x + threadIdx.x;
    if (e >= E) return;
    int d = g_is64 ? ei[2 * (E + e)] : ei[E + e];   // low word (little-endian)
    atomicAdd(&g_deg[d], ew[e]);
    atomicAdd(&g_cnt[d], 1);
}

__global__ void dinv_kernel(int n) {
    int i = blockIdx.x * blockDim.x + threadIdx.x;
    if (i < n) g_dinv[i] = rsqrtf(g_deg[i]);   // deg >= 1 always
}

// -------- exclusive scan of g_cnt -> g_rowptr (3 phases, 1024 elems/block) ---
__global__ void scan_phase1(int n) {
    __shared__ int sd[256];
    int tid = threadIdx.x;
    int base = blockIdx.x * 1024 + tid * 4;
    int s = 0;
    #pragma unroll
    for (int j = 0; j < 4; j++) if (base + j < n) s += g_cnt[base + j];
    sd[tid] = s; __syncthreads();
    for (int off = 128; off > 0; off >>= 1) {
        if (tid < off) sd[tid] += sd[tid + off];
        __syncthreads();
    }
    if (tid == 0) g_bsum[blockIdx.x] = sd[0];
}

__global__ void scan_phase2(int nblocks, int n, int E) {
    if (threadIdx.x == 0) {
        int acc = 0;
        for (int i = 0; i < nblocks; i++) { g_boff[i] = acc; acc += g_bsum[i]; }
        g_rowptr[n] = E;
    }
}

__global__ void scan_phase3(int n) {
    __shared__ int sd[256];
    int tid = threadIdx.x;
    int base = blockIdx.x * 1024 + tid * 4;
    int c[4]; int s = 0;
    #pragma unroll
    for (int j = 0; j < 4; j++) {
        c[j] = (base + j < n) ? g_cnt[base + j] : 0;
        s += c[j];
    }
    sd[tid] = s; __syncthreads();
    // Hillis-Steele inclusive scan
    for (int off = 1; off < 256; off <<= 1) {
        int v = (tid >= off) ? sd[tid - off] : 0;
        __syncthreads();
        sd[tid] += v;
        __syncthreads();
    }
    int run = g_boff[blockIdx.x] + ((tid == 0) ? 0 : sd[tid - 1]);
    #pragma unroll
    for (int j = 0; j < 4; j++) {
        if (base + j < n) {
            g_rowptr[base + j] = run;
            g_fill[base + j]   = run;
            run += c[j];
        }
    }
}

// scatter edges into CSR grouped by dst, with precomputed norm
__global__ void scatter_kernel(const int* __restrict__ ei,
                               const float* __restrict__ ew, int E) {
    int e = blockIdx.x * blockDim.x + threadIdx.x;
    if (e >= E) return;
    int s, d;
    if (g_is64) { s = ei[2 * e]; d = ei[2 * (E + e)]; }
    else        { s = ei[e];     d = ei[E + e]; }
    float nm = g_dinv[s] * ew[e] * g_dinv[d];
    int pos = atomicAdd(&g_fill[d], 1);
    g_srcs[pos]  = s;
    g_norms[pos] = nm;
}

// ---------------- GEMM: H[n,128] = X[n,128] @ W[128,128] ---------------------
// 4 rows per warp; packed fp32 FFMA2 (fma.rn.f32x2) for 2 MACs/inst.
__global__ void gemm128_kernel(const float* __restrict__ X,
                               const float* __restrict__ W,
                               float* __restrict__ H, int n) {
    int warp = (blockIdx.x * blockDim.x + threadIdx.x) >> 5;
    int lane = threadIdx.x & 31;
    int r0 = warp * 4;
    if (r0 >= n) return;

    const float4*     X4 = (const float4*)X;
    const ulonglong2* Wp = (const ulonglong2*)W;   // W row = 32 x 16B

    float4 xr[4];
    #pragma unroll
    for (int r = 0; r < 4; r++) {
        int row = (r0 + r < n) ? (r0 + r) : r0;
        xr[r] = __ldcs(X4 + (size_t)row * 32 + lane);
    }

    unsigned long long acc[4][2] = {};

    #pragma unroll 2
    for (int kb = 0; kb < 32; kb++) {
        float a[4][4];
        #pragma unroll
        for (int r = 0; r < 4; r++) {
            a[r][0] = __shfl_sync(0xffffffffu, xr[r].x, kb);
            a[r][1] = __shfl_sync(0xffffffffu, xr[r].y, kb);
            a[r][2] = __shfl_sync(0xffffffffu, xr[r].z, kb);
            a[r][3] = __shfl_sync(0xffffffffu, xr[r].w, kb);
        }
        #pragma unroll
        for (int c = 0; c < 4; c++) {
            ulonglong2 w = __ldg(Wp + (size_t)(kb * 4 + c) * 32 + lane);
            #pragma unroll
            for (int r = 0; r < 4; r++) {
                unsigned long long av = pack2(a[r][c]);
                ffma2(acc[r][0], av, w.x);
                ffma2(acc[r][1], av, w.y);
            }
        }
    }
    #pragma unroll
    for (int r = 0; r < 4; r++) {
        if (r0 + r < n)
            ((ulonglong2*)H)[(size_t)(r0 + r) * 32 + lane] =
                make_ulonglong2(acc[r][0], acc[r][1]);
    }
}

// ---------------- fused aggregation + self-loop + bias + relu ----------------
// One warp per dst node; CSR row accumulate in registers; single output write.
__global__ void agg_kernel(const float* __restrict__ h,
                           const float* __restrict__ b,
                           float* __restrict__ out, int n) {
    int d = (int)(((size_t)blockIdx.x * blockDim.x + threadIdx.x) >> 5);
    int lane = threadIdx.x & 31;
    if (d >= n) return;

    const float4* h4 = (const float4*)h;
    float dv = g_dinv[d];
    float self = dv * dv;

    float4 acc = __ldg(h4 + (size_t)d * 32 + lane);
    acc.x *= self; acc.y *= self; acc.z *= self; acc.w *= self;
    float4 acc2 = make_float4(0.f, 0.f, 0.f, 0.f);

    int i   = g_rowptr[d];
    int end = g_rowptr[d + 1];
    for (; i + 2 <= end; i += 2) {
        int   s0 = g_srcs[i],     s1 = g_srcs[i + 1];
        float n0 = g_norms[i],    n1 = g_norms[i + 1];
        float4 h0 = __ldg(h4 + (size_t)s0 * 32 + lane);
        float4 h1 = __ldg(h4 + (size_t)s1 * 32 + lane);
        acc.x  = fmaf(h0.x, n0, acc.x);  acc.y  = fmaf(h0.y, n0, acc.y);
        acc.z  = fmaf(h0.z, n0, acc.z);  acc.w  = fmaf(h0.w, n0, acc.w);
        acc2.x = fmaf(h1.x, n1, acc2.x); acc2.y = fmaf(h1.y, n1, acc2.y);
        acc2.z = fmaf(h1.z, n1, acc2.z); acc2.w = fmaf(h1.w, n1, acc2.w);
    }
    if (i < end) {
        int s0 = g_srcs[i]; float n0 = g_norms[i];
        float4 h0 = __ldg(h4 + (size_t)s0 * 32 + lane);
        acc.x = fmaf(h0.x, n0, acc.x); acc.y = fmaf(h0.y, n0, acc.y);
        acc.z = fmaf(h0.z, n0, acc.z); acc.w = fmaf(h0.w, n0, acc.w);
    }
    acc.x += acc2.x; acc.y += acc2.y; acc.z += acc2.z; acc.w += acc2.w;

    float4 bv = __ldg((const float4*)b + lane);
    acc.x = fmaxf(acc.x + bv.x, 0.f);
    acc.y = fmaxf(acc.y + bv.y, 0.f);
    acc.z = fmaxf(acc.z + bv.z, 0.f);
    acc.w = fmaxf(acc.w + bv.w, 0.f);
    ((float4*)out)[(size_t)d * 32 + lane] = acc;
}

// ---------------- launch -----------------------------------------------------
extern "C" void kernel_launch(void* const* d_in, const int* in_sizes, int n_in,
                              void* d_out, int out_size) {
    const float* x  = (const float*)d_in[0];
    const int*   ei = (const int*)d_in[1];
    const float* ew = (const float*)d_in[2];
    const float* W1 = (const float*)d_in[3];
    const float* b1 = (const float*)d_in[4];
    const float* W2 = (const float*)d_in[5];
    const float* b2 = (const float*)d_in[6];
    float* out = (float*)d_out;

    const int N = in_sizes[0] / DD;   // 100000
    const int E = in_sizes[2];        // 1600000

    float* h = nullptr; cudaGetSymbolAddress((void**)&h, g_h);
    float* y = nullptr; cudaGetSymbolAddress((void**)&y, g_y);

    const int T = 256;
    int nodeBlocks = (N + T - 1) / T;
    int edgeBlocks = (E + T - 1) / T;
    int scanBlocks = (N + 1023) / 1024;
    int gemmBlocks = (((N + 3) / 4) * 32 + T - 1) / T;     // 4 rows/warp
    int aggBlocks  = (int)(((size_t)N * 32 + T - 1) / T);  // warp/node

    // preprocessing: degree, dinv, CSR build (shared by both layers)
    detect_kernel<<<1, 32>>>(ei);
    node_init_kernel<<<nodeBlocks, T>>>(N);
    deg_edge_kernel<<<edgeBlocks, T>>>(ei, ew, E);
    dinv_kernel<<<nodeBlocks, T>>>(N);
    scan_phase1<<<scanBlocks, 256>>>(N);
    scan_phase2<<<1, 32>>>(scanBlocks, N, E);
    scan_phase3<<<scanBlocks, 256>>>(N);
    scatter_kernel<<<edgeBlocks, T>>>(ei, ew, E);

    // ---- layer 1 ----
    gemm128_kernel<<<gemmBlocks, T>>>(x, W1, h, N);
    agg_kernel<<<aggBlocks, T>>>(h, b1, y, N);

    // ---- layer 2 ----
    gemm128_kernel<<<gemmBlocks, T>>>(y, W2, h, N);
    agg_kernel<<<aggBlocks, T>>>(h, b2, out, N);
}